// round 15
// baseline (speedup 1.0000x reference)
#include <cuda_runtime.h>
#include <cuda_fp16.h>
#include <math.h>
#include <stdint.h>

// ---------------------------------------------------------------------------
// Problem constants
// ---------------------------------------------------------------------------
#define L     4096
#define HID   2560
#define NH    8
#define NKV   4
#define HD    256
#define QD    (NH*HD)    // 2048
#define KD    (NKV*HD)   // 1024
#define QKVD  (QD + 2*KD) // 4096
#define SCALING 0.0625f
#define SEQ   1024

// ---------------------------------------------------------------------------
// Scratch
// ---------------------------------------------------------------------------
__device__ float g_QKV[L * QKVD];
__device__ __half g_hs16[L * HID];
__device__ __half g_Wqkv16[QKVD * HID];
__device__ __half g_Wo16[HID * QD];
__device__ __half g_A16[L * QD];
__device__ __half g_Q16a[L * QD];
__device__ __half g_K16a[L * KD];
__device__ __half g_V16a[L * KD];

// ---------------------------------------------------------------------------
// helpers
// ---------------------------------------------------------------------------
__device__ __forceinline__ void mma16h(float* c, const uint32_t* a, const uint32_t* b) {
    asm volatile(
        "mma.sync.aligned.m16n8k16.row.col.f32.f16.f16.f32 "
        "{%0,%1,%2,%3}, {%4,%5,%6,%7}, {%8,%9}, {%0,%1,%2,%3};"
        : "+f"(c[0]), "+f"(c[1]), "+f"(c[2]), "+f"(c[3])
        : "r"(a[0]), "r"(a[1]), "r"(a[2]), "r"(a[3]), "r"(b[0]), "r"(b[1]));
}
__device__ __forceinline__ void ldsm4(uint32_t* r, uint32_t addr) {
    asm volatile("ldmatrix.sync.aligned.m8n8.x4.shared.b16 {%0,%1,%2,%3}, [%4];"
                 : "=r"(r[0]), "=r"(r[1]), "=r"(r[2]), "=r"(r[3]) : "r"(addr));
}
__device__ __forceinline__ void ldsm4t(uint32_t* r, uint32_t addr) {
    asm volatile("ldmatrix.sync.aligned.m8n8.x4.trans.shared.b16 {%0,%1,%2,%3}, [%4];"
                 : "=r"(r[0]), "=r"(r[1]), "=r"(r[2]), "=r"(r[3]) : "r"(addr));
}
__device__ __forceinline__ void cpasync16(uint32_t s, const void* g) {
    asm volatile("cp.async.cg.shared.global [%0], [%1], 16;" :: "r"(s), "l"(g));
}

// ---------------------------------------------------------------------------
// prep kernels (frozen)
// ---------------------------------------------------------------------------
__global__ void conv_h_kernel(const float* __restrict__ in,
                              __half* __restrict__ out, int n4)
{
    int i = blockIdx.x * blockDim.x + threadIdx.x;
    if (i >= n4) return;
    float4 v = ((const float4*)in)[i];
    ((__half2*)out)[2 * i]     = __half2(__float2half_rn(v.x), __float2half_rn(v.y));
    ((__half2*)out)[2 * i + 1] = __half2(__float2half_rn(v.z), __float2half_rn(v.w));
}

__global__ void transpose_qkv_kernel(const float* __restrict__ Wq,
                                     const float* __restrict__ Wk,
                                     const float* __restrict__ Wv,
                                     __half* __restrict__ T)
{
    __shared__ float t[32][33];
    const int z = blockIdx.z;
    const int Ndim = (z == 0) ? QD : KD;
    const int n0 = blockIdx.x * 32;
    if (n0 >= Ndim) return;
    const int k0 = blockIdx.y * 32;
    const float* W = (z == 0) ? Wq : (z == 1 ? Wk : Wv);
    __half* To = T + (size_t)((z == 0) ? 0 : (z == 1 ? QD : QD + KD)) * HID;
    const int tx = threadIdx.x, ty = threadIdx.y;
#pragma unroll
    for (int j = 0; j < 4; j++)
        t[ty + j * 8][tx] = W[(size_t)(k0 + ty + j * 8) * Ndim + n0 + tx];
    __syncthreads();
#pragma unroll
    for (int j = 0; j < 4; j++)
        To[(size_t)(n0 + ty + j * 8) * HID + k0 + tx] = __float2half_rn(t[tx][ty + j * 8]);
}

__global__ void transpose_h_kernel(const float* __restrict__ W,
                                   __half* __restrict__ T, int Kdim, int Ndim)
{
    __shared__ float t[32][33];
    const int k0 = blockIdx.y * 32, n0 = blockIdx.x * 32;
    const int tx = threadIdx.x, ty = threadIdx.y;
#pragma unroll
    for (int j = 0; j < 4; j++)
        t[ty + j * 8][tx] = W[(size_t)(k0 + ty + j * 8) * Ndim + n0 + tx];
    __syncthreads();
#pragma unroll
    for (int j = 0; j < 4; j++)
        T[(size_t)(n0 + ty + j * 8) * Kdim + k0 + tx] = __float2half_rn(t[tx][ty + j * 8]);
}

// ---------------------------------------------------------------------------
// single-fp16 GEMM (round-8 proven, frozen)
// ---------------------------------------------------------------------------
#define SAB 72
#define TILE_E (128*SAB)
#define STG_E (2*TILE_E)
#define HGSM (2*STG_E*2)

__global__ __launch_bounds__(256, 2)
void hgemm(const __half* __restrict__ Ap, const __half* __restrict__ Bp,
           float* __restrict__ C, int Ntot, int K)
{
    extern __shared__ __half sh16[];
    const int tid  = threadIdx.x;
    const int lane = tid & 31, wid = tid >> 5;
    const int wm = wid >> 2, wn = wid & 3;
    const int g = lane >> 2, t = lane & 3;
    const int m0 = blockIdx.y * 128, n0 = blockIdx.x * 128;

    const uint32_t sbase = (uint32_t)__cvta_generic_to_shared(sh16);
    const __half* baseA = Ap + (size_t)m0 * K;
    const __half* baseB = Bp + (size_t)n0 * K;

    float acc[4][4][4];
#pragma unroll
    for (int mt = 0; mt < 4; mt++)
#pragma unroll
        for (int nt = 0; nt < 4; nt++)
#pragma unroll
            for (int r = 0; r < 4; r++) acc[mt][nt][r] = 0.f;

    const int a_off = ((lane & 7) + ((lane >> 3) & 1) * 8) * SAB + ((lane >> 4) & 1) * 8;
    const int b_off = ((lane & 7) + ((lane >> 4) & 1) * 8) * SAB + ((lane >> 3) & 1) * 8;

    auto issue_copy = [&](int c, int buf) {
        const int koff = c * 64;
#pragma unroll
        for (int i = 0; i < 8; i++) {
            const int f = tid + i * 256;
            const int tl = f >> 10;
            const int slot = f & 1023;
            const int row = slot >> 3, seg = slot & 7;
            const __half* gp = (tl ? baseB : baseA) + (size_t)row * K + koff + seg * 8;
            const uint32_t dst = sbase +
                (uint32_t)(buf * STG_E + tl * TILE_E + row * SAB + seg * 8) * 2;
            cpasync16(dst, gp);
        }
        asm volatile("cp.async.commit_group;" ::: "memory");
    };

    const int nkb = K >> 6;
    issue_copy(0, 0);

    for (int kb = 0; kb < nkb; kb++) {
        const int cur = kb & 1;
        if (kb + 1 < nkb) {
            issue_copy(kb + 1, cur ^ 1);
            asm volatile("cp.async.wait_group 1;" ::: "memory");
        } else {
            asm volatile("cp.async.wait_group 0;" ::: "memory");
        }
        __syncthreads();

        const uint32_t sA = sbase + (uint32_t)(cur * STG_E) * 2;
        const uint32_t sB = sA + (uint32_t)TILE_E * 2;

#pragma unroll
        for (int ks = 0; ks < 4; ks++) {
            const int kbase = ks * 16;
            uint32_t af[4][4], bf[2][4];
#pragma unroll
            for (int mt = 0; mt < 4; mt++)
                ldsm4(af[mt], sA + (uint32_t)((wm * 64 + mt * 16) * SAB + kbase + a_off) * 2);
#pragma unroll
            for (int np = 0; np < 2; np++)
                ldsm4(bf[np], sB + (uint32_t)((wn * 32 + np * 16) * SAB + kbase + b_off) * 2);
#pragma unroll
            for (int mt = 0; mt < 4; mt++)
#pragma unroll
                for (int nt = 0; nt < 4; nt++) {
                    const int pr = nt >> 1, hf = (nt & 1) * 2;
                    uint32_t bb[2] = { bf[pr][hf], bf[pr][hf + 1] };
                    mma16h(acc[mt][nt], af[mt], bb);
                }
        }
        __syncthreads();
    }

#pragma unroll
    for (int mt = 0; mt < 4; mt++) {
        const int r0 = m0 + wm * 64 + mt * 16 + g;
#pragma unroll
        for (int nt = 0; nt < 4; nt++) {
            const int c0 = n0 + wn * 32 + nt * 8 + t * 2;
            *(float2*)&C[(size_t)r0 * Ntot + c0] =
                make_float2(acc[mt][nt][0], acc[mt][nt][1]);
            *(float2*)&C[(size_t)(r0 + 8) * Ntot + c0] =
                make_float2(acc[mt][nt][2], acc[mt][nt][3]);
        }
    }
}

// ---------------------------------------------------------------------------
// Unified norm/rope -> fp16 single (frozen)
// ---------------------------------------------------------------------------
__global__ __launch_bounds__(256)
void prep_qkv_kernel(const float* __restrict__ QKV,
                     const float* __restrict__ qw,
                     const float* __restrict__ kw,
                     const float* __restrict__ cosp,
                     const float* __restrict__ sinp,
                     __half* __restrict__ Qo, __half* __restrict__ Ko,
                     __half* __restrict__ Vo)
{
    const int t = blockIdx.x;
    const int h = blockIdx.y;
    const int d = threadIdx.x;

    if (h >= 12) {
        const int hv = h - 12;
        float x = QKV[(size_t)t * QKVD + QD + KD + hv * HD + d];
        Vo[(size_t)t * KD + hv * HD + d] = __float2half_rn(x);
        return;
    }

    const bool isQ = (h < 8);
    const int hh = isQ ? h : h - 8;
    const float* w = isQ ? qw : kw;
    float x = QKV[(size_t)t * QKVD + (isQ ? 0 : QD) + hh * HD + d];

    float v = x * x;
#pragma unroll
    for (int o = 16; o; o >>= 1) v += __shfl_xor_sync(0xffffffffu, v, o);

    __shared__ float ws[8];
    __shared__ float buf[HD];
    if ((d & 31) == 0) ws[d >> 5] = v;
    __syncthreads();
    float ss = ws[0] + ws[1] + ws[2] + ws[3] + ws[4] + ws[5] + ws[6] + ws[7];

    float r = rsqrtf(ss * (1.0f / HD) + 1e-6f);
    float xn = x * r * (1.0f + w[d]);
    buf[d] = xn;
    __syncthreads();

    float rot = (d < HD / 2) ? -buf[d + HD / 2] : buf[d - HD / 2];
    float c = cosp[(size_t)t * HD + d];
    float s = sinp[(size_t)t * HD + d];
    float xr = xn * c + rot * s;

    const size_t oo = (size_t)t * (isQ ? QD : KD) + hh * HD + d;
    if (isQ) Qo[oo] = __float2half_rn(xr);
    else     Ko[oo] = __float2half_rn(xr);
}

// ---------------------------------------------------------------------------
// Flash attention, single fp16, BM=64 x BN=128, d-chunks of 128 (2 per phase).
// Syncs per kt-iter: 10 (was 18). smem ~122 KB, 1 CTA/SM.
// ---------------------------------------------------------------------------
#define SQF 264
#define SCF2 136
#define SPF 136
#define CHUNK2_E (128*SCF2)            // 17408 halves per K/V chunk
#define OQ3  0                         // Q: 64*SQF = 16896
#define OC3  (64*SQF)                  // 2 chunk slots
#define OP3  (OC3 + 2*CHUNK2_E)        // P: 64*SPF
#define OEND3 (OP3 + 64*SPF)           // 60416 halves
#define ATTH_SMEM (OEND3*2 + 256*4)    // 121856 bytes

__global__ __launch_bounds__(256, 1)
void attn_h_kernel()
{
    extern __shared__ __half smh[];
    float* pm = (float*)(smh + OEND3);
    float* ps = pm + 128;

    const int qt  = (int)gridDim.x - 1 - (int)blockIdx.x;  // long rows first
    const int seq = blockIdx.y;
    const int h   = blockIdx.z;
    const int kvh = h >> 1;

    const int tid  = threadIdx.x;
    const int lane = tid & 31, wid = tid >> 5;
    const int wm = wid >> 1, wn = wid & 1;
    const int g = lane >> 2, t = lane & 3;

    const int t0 = seq * SEQ + qt * 64;
    const int ktmax = qt >> 1;
    const int doff = (qt & 1) * 64;
    const uint32_t sb = (uint32_t)__cvta_generic_to_shared(smh);

    const int aoffQ = ((lane & 7) + ((lane >> 3) & 1) * 8) * SQF + ((lane >> 4) & 1) * 8;
    const int aoffP = ((lane & 7) + ((lane >> 3) & 1) * 8) * SPF + ((lane >> 4) & 1) * 8;
    const int boffK = ((lane & 7) + ((lane >> 4) & 1) * 8) * SCF2 + ((lane >> 3) & 1) * 8;
    const int voffV = ((lane & 7) + ((lane >> 3) & 1) * 8) * SCF2 + ((lane >> 4) & 1) * 8;

    // load one 128-row x 128-d fp16 chunk of K or V into slot buf
    auto issue_kv = [&](const __half* gsrc, int k0, int dc, int buf) {
#pragma unroll
        for (int i = 0; i < 8; i++) {
            int f = tid + i * 256;          // 0..2047
            int row = f >> 4, seg = f & 15;
            const __half* gp = gsrc +
                (size_t)(k0 + row) * KD + kvh * HD + dc * 128 + seg * 8;
            cpasync16(sb + (uint32_t)(OC3 + buf * CHUNK2_E + row * SCF2 + seg * 8) * 2, gp);
        }
        asm volatile("cp.async.commit_group;" ::: "memory");
    };

    // prefetch K chunk0 of kt=0, then resident Q
    issue_kv(g_K16a, seq * SEQ, 0, 0);
    {
        const __half* gq = g_Q16a + (size_t)t0 * QD + h * HD;
#pragma unroll
        for (int i = 0; i < 8; i++) {
            int f = tid + i * 256;
            int row = f >> 5, seg = f & 31;
            cpasync16(sb + (uint32_t)(OQ3 + row * SQF + seg * 8) * 2,
                      gq + (size_t)row * QD + seg * 8);
        }
        asm volatile("cp.async.commit_group;" ::: "memory");
        asm volatile("cp.async.wait_group 0;" ::: "memory");
    }
    __syncthreads();

    float O[4][4][4];    // [64-d group 0..3][nt][reg]
#pragma unroll
    for (int dg = 0; dg < 4; dg++)
#pragma unroll
        for (int nt = 0; nt < 4; nt++)
#pragma unroll
            for (int r = 0; r < 4; r++) O[dg][nt][r] = 0.f;
    float m0 = -INFINITY, m1 = -INFINITY, l0 = 0.f, l1 = 0.f;

    for (int kt = 0; kt <= ktmax; kt++) {
        const int k0 = seq * SEQ + kt * 128;

        float S[8][4];
#pragma unroll
        for (int nt = 0; nt < 8; nt++)
#pragma unroll
            for (int r = 0; r < 4; r++) S[nt][r] = 0.f;

        // ---- S = Q @ K^T over 2 d-chunks of 128 ----
        for (int dc = 0; dc < 2; dc++) {
            if (dc == 0) {
                issue_kv(g_K16a, k0, 1, 1);
                asm volatile("cp.async.wait_group 1;" ::: "memory");
            } else {
                asm volatile("cp.async.wait_group 0;" ::: "memory");
            }
            __syncthreads();

            const int ok = OC3 + dc * CHUNK2_E;
#pragma unroll
            for (int ks = 0; ks < 8; ks++) {
                const int kq = dc * 128 + ks * 16;
                uint32_t qf[4], kf[4][4];
                ldsm4(qf, sb + (uint32_t)(OQ3 + (wm * 16) * SQF + kq + aoffQ) * 2);
#pragma unroll
                for (int pr = 0; pr < 4; pr++) {
                    const int nb = (wn * 64 + pr * 16) * SCF2 + ks * 16;
                    ldsm4(kf[pr], sb + (uint32_t)(ok + nb + boffK) * 2);
                }
#pragma unroll
                for (int nt = 0; nt < 8; nt++) {
                    const int pr = nt >> 1, hf = (nt & 1) * 2;
                    uint32_t bb[2] = { kf[pr][hf], kf[pr][hf + 1] };
                    mma16h(S[nt], qf, bb);
                }
            }
            __syncthreads();
        }

        // V chunk0 prefetch overlaps softmax
        issue_kv(g_V16a, k0, 0, 0);

        // ---- scale + causal mask (last k-tile only) ----
#pragma unroll
        for (int nt = 0; nt < 8; nt++) {
#pragma unroll
            for (int r = 0; r < 4; r++) S[nt][r] *= SCALING;
            if (kt == ktmax) {
                const int cl = wn * 64 + nt * 8 + 2 * t;
                const int rl0 = wm * 16 + g + doff, rl1 = rl0 + 8;
                if (cl     > rl0) S[nt][0] = -INFINITY;
                if (cl + 1 > rl0) S[nt][1] = -INFINITY;
                if (cl     > rl1) S[nt][2] = -INFINITY;
                if (cl + 1 > rl1) S[nt][3] = -INFINITY;
            }
        }

        // ---- online softmax ----
        float rm0 = -INFINITY, rm1 = -INFINITY;
#pragma unroll
        for (int nt = 0; nt < 8; nt++) {
            rm0 = fmaxf(rm0, fmaxf(S[nt][0], S[nt][1]));
            rm1 = fmaxf(rm1, fmaxf(S[nt][2], S[nt][3]));
        }
        rm0 = fmaxf(rm0, __shfl_xor_sync(0xffffffffu, rm0, 1));
        rm0 = fmaxf(rm0, __shfl_xor_sync(0xffffffffu, rm0, 2));
        rm1 = fmaxf(rm1, __shfl_xor_sync(0xffffffffu, rm1, 1));
        rm1 = fmaxf(rm1, __shfl_xor_sync(0xffffffffu, rm1, 2));
        if (t == 0) {
            pm[wn * 64 + wm * 16 + g]     = rm0;
            pm[wn * 64 + wm * 16 + 8 + g] = rm1;
        }
        __syncthreads();
        rm0 = fmaxf(rm0, pm[(wn ^ 1) * 64 + wm * 16 + g]);
        rm1 = fmaxf(rm1, pm[(wn ^ 1) * 64 + wm * 16 + 8 + g]);

        const float mn0 = fmaxf(m0, rm0), mn1 = fmaxf(m1, rm1);
        const float a0 = __expf(m0 - mn0), a1 = __expf(m1 - mn1);

        float s0 = 0.f, s1 = 0.f;
#pragma unroll
        for (int nt = 0; nt < 8; nt++) {
            float p0 = __expf(S[nt][0] - mn0);
            float p1 = __expf(S[nt][1] - mn0);
            float p2 = __expf(S[nt][2] - mn1);
            float p3 = __expf(S[nt][3] - mn1);
            s0 += p0 + p1;
            s1 += p2 + p3;
            const int col = wn * 64 + nt * 8 + 2 * t;
            const int r0 = wm * 16 + g, r1 = r0 + 8;
            *(__half2*)&smh[OP3 + r0 * SPF + col] = __floats2half2_rn(p0, p1);
            *(__half2*)&smh[OP3 + r1 * SPF + col] = __floats2half2_rn(p2, p3);
        }
        s0 += __shfl_xor_sync(0xffffffffu, s0, 1);
        s0 += __shfl_xor_sync(0xffffffffu, s0, 2);
        s1 += __shfl_xor_sync(0xffffffffu, s1, 1);
        s1 += __shfl_xor_sync(0xffffffffu, s1, 2);
        if (t == 0) {
            ps[wn * 64 + wm * 16 + g]     = s0;
            ps[wn * 64 + wm * 16 + 8 + g] = s1;
        }
        __syncthreads();
        l0 = l0 * a0 + ps[wm * 16 + g]     + ps[64 + wm * 16 + g];
        l1 = l1 * a1 + ps[wm * 16 + 8 + g] + ps[64 + wm * 16 + 8 + g];
        m0 = mn0; m1 = mn1;
#pragma unroll
        for (int dg = 0; dg < 4; dg++)
#pragma unroll
            for (int nt = 0; nt < 4; nt++) {
                O[dg][nt][0] *= a0; O[dg][nt][1] *= a0;
                O[dg][nt][2] *= a1; O[dg][nt][3] *= a1;
            }

        // ---- O += P @ V over 2 d-chunks of 128; prefetch next-kt K ----
        for (int dc = 0; dc < 2; dc++) {
            if (dc == 0) {
                issue_kv(g_V16a, k0, 1, 1);
                asm volatile("cp.async.wait_group 1;" ::: "memory");
            } else {
                asm volatile("cp.async.wait_group 0;" ::: "memory");
                if (kt < ktmax) issue_kv(g_K16a, k0 + 128, 0, 0);
            }
            __syncthreads();

            const int ok = OC3 + dc * CHUNK2_E;
#pragma unroll
            for (int kk = 0; kk < 8; kk++) {
                uint32_t pf[4], vf[2][2][4];    // [half][pr]
                ldsm4(pf, sb + (uint32_t)(OP3 + (wm * 16) * SPF + kk * 16 + aoffP) * 2);
#pragma unroll
                for (int hlf = 0; hlf < 2; hlf++)
#pragma unroll
                    for (int pr = 0; pr < 2; pr++) {
                        const int vb = (kk * 16) * SCF2 + hlf * 64 + wn * 32 + pr * 16;
                        ldsm4t(vf[hlf][pr], sb + (uint32_t)(ok + vb + voffV) * 2);
                    }
#pragma unroll
                for (int hlf = 0; hlf < 2; hlf++)
#pragma unroll
                    for (int nt = 0; nt < 4; nt++) {
                        const int pr = nt >> 1, hf = (nt & 1) * 2;
                        uint32_t bb[2] = { vf[hlf][pr][hf], vf[hlf][pr][hf + 1] };
                        mma16h(O[dc * 2 + hlf][nt], pf, bb);
                    }
            }
            __syncthreads();
        }
    }

    // ---- epilogue: fp16 direct ----
    const float i0 = 1.0f / l0, i1 = 1.0f / l1;
#pragma unroll
    for (int dg = 0; dg < 4; dg++)
#pragma unroll
        for (int nt = 0; nt < 4; nt++) {
            const int col = h * HD + dg * 64 + wn * 32 + nt * 8 + 2 * t;
            const size_t r0 = (size_t)(t0 + wm * 16 + g) * QD + col;
            const size_t r1 = (size_t)(t0 + wm * 16 + 8 + g) * QD + col;
            *(__half2*)&g_A16[r0] =
                __floats2half2_rn(O[dg][nt][0] * i0, O[dg][nt][1] * i0);
            *(__half2*)&g_A16[r1] =
                __floats2half2_rn(O[dg][nt][2] * i1, O[dg][nt][3] * i1);
        }
}

// ---------------------------------------------------------------------------
// launch
// ---------------------------------------------------------------------------
extern "C" void kernel_launch(void* const* d_in, const int* in_sizes, int n_in,
                              void* d_out, int out_size)
{
    (void)in_sizes; (void)n_in; (void)out_size;
    const float* hs   = (const float*)d_in[0];
    const float* cosp = (const float*)d_in[1];
    const float* sinp = (const float*)d_in[2];
    const float* Wq   = (const float*)d_in[3];
    const float* Wk   = (const float*)d_in[4];
    const float* Wv   = (const float*)d_in[5];
    const float* Wo   = (const float*)d_in[6];
    const float* qw   = (const float*)d_in[7];
    const float* kw   = (const float*)d_in[8];
    float* out = (float*)d_out;

    float *pQKV;
    __half *phs, *pWqkv, *pWo, *pA16, *pQ16, *pK16, *pV16;
    cudaGetSymbolAddress((void**)&pQKV, g_QKV);
    cudaGetSymbolAddress((void**)&phs,  g_hs16);
    cudaGetSymbolAddress((void**)&pWqkv, g_Wqkv16);
    cudaGetSymbolAddress((void**)&pWo,  g_Wo16);
    cudaGetSymbolAddress((void**)&pA16, g_A16);
    cudaGetSymbolAddress((void**)&pQ16, g_Q16a);
    cudaGetSymbolAddress((void**)&pK16, g_K16a);
    cudaGetSymbolAddress((void**)&pV16, g_V16a);

    // 0. operand prep
    {
        int n = L * HID / 4;
        conv_h_kernel<<<(n + 255) / 256, 256>>>(hs, phs, n);
    }
    transpose_qkv_kernel<<<dim3(QD / 32, HID / 32, 3), dim3(32, 8)>>>(Wq, Wk, Wv, pWqkv);
    transpose_h_kernel<<<dim3(HID / 32, QD / 32), dim3(32, 8)>>>(Wo, pWo, QD, HID);

    cudaFuncSetAttribute(hgemm, cudaFuncAttributeMaxDynamicSharedMemorySize, HGSM);

    // 1. fused QKV projection
    hgemm<<<dim3(QKVD / 128, L / 128), 256, HGSM>>>(phs, pWqkv, pQKV, QKVD, HID);

    // 2. unified RMSNorm/RoPE/V-convert -> fp16 single
    prep_qkv_kernel<<<dim3(L, 16), 256>>>(pQKV, qw, kw, cosp, sinp,
                                          pQ16, pK16, pV16);

    // 3. attention (single fp16, BN=128, 128-d chunks)
    cudaFuncSetAttribute(attn_h_kernel,
                         cudaFuncAttributeMaxDynamicSharedMemorySize, ATTH_SMEM);
    attn_h_kernel<<<dim3(SEQ / 64, L / SEQ, NH), 256, ATTH_SMEM>>>();

    // 4. output projection
    hgemm<<<dim3(HID / 128, L / 128), 256, HGSM>>>(pA16, pWo, out, HID, QD);
}

// round 16
// speedup vs baseline: 1.0239x; 1.0239x over previous
#include <cuda_runtime.h>
#include <cuda_fp16.h>
#include <math.h>
#include <stdint.h>

// ---------------------------------------------------------------------------
// Problem constants
// ---------------------------------------------------------------------------
#define L     4096
#define HID   2560
#define NH    8
#define NKV   4
#define HD    256
#define QD    (NH*HD)    // 2048
#define KD    (NKV*HD)   // 1024
#define QKVD  (QD + 2*KD) // 4096
#define SCALING 0.0625f
#define SEQ   1024

// ---------------------------------------------------------------------------
// Scratch
// ---------------------------------------------------------------------------
__device__ __half g_QKV16[L * QKVD];    // fused projection output, fp16
__device__ __half g_hs16[L * HID];
__device__ __half g_Wqkv16[QKVD * HID];
__device__ __half g_Wo16[HID * QD];
__device__ __half g_A16[L * QD];
__device__ __half g_Q16a[L * QD];       // post-norm/rope Q
__device__ __half g_K16a[L * KD];       // post-norm/rope K
// V lives inside g_QKV16 (cols QD+KD .. QKVD), no copy

// ---------------------------------------------------------------------------
// helpers
// ---------------------------------------------------------------------------
__device__ __forceinline__ void mma16h(float* c, const uint32_t* a, const uint32_t* b) {
    asm volatile(
        "mma.sync.aligned.m16n8k16.row.col.f32.f16.f16.f32 "
        "{%0,%1,%2,%3}, {%4,%5,%6,%7}, {%8,%9}, {%0,%1,%2,%3};"
        : "+f"(c[0]), "+f"(c[1]), "+f"(c[2]), "+f"(c[3])
        : "r"(a[0]), "r"(a[1]), "r"(a[2]), "r"(a[3]), "r"(b[0]), "r"(b[1]));
}
__device__ __forceinline__ void ldsm4(uint32_t* r, uint32_t addr) {
    asm volatile("ldmatrix.sync.aligned.m8n8.x4.shared.b16 {%0,%1,%2,%3}, [%4];"
                 : "=r"(r[0]), "=r"(r[1]), "=r"(r[2]), "=r"(r[3]) : "r"(addr));
}
__device__ __forceinline__ void ldsm4t(uint32_t* r, uint32_t addr) {
    asm volatile("ldmatrix.sync.aligned.m8n8.x4.trans.shared.b16 {%0,%1,%2,%3}, [%4];"
                 : "=r"(r[0]), "=r"(r[1]), "=r"(r[2]), "=r"(r[3]) : "r"(addr));
}
__device__ __forceinline__ void cpasync16(uint32_t s, const void* g) {
    asm volatile("cp.async.cg.shared.global [%0], [%1], 16;" :: "r"(s), "l"(g));
}

// ---------------------------------------------------------------------------
// prep kernels
// ---------------------------------------------------------------------------
__global__ void conv_h_kernel(const float* __restrict__ in,
                              __half* __restrict__ out, int n4)
{
    int i = blockIdx.x * blockDim.x + threadIdx.x;
    if (i >= n4) return;
    float4 v = ((const float4*)in)[i];
    ((__half2*)out)[2 * i]     = __half2(__float2half_rn(v.x), __float2half_rn(v.y));
    ((__half2*)out)[2 * i + 1] = __half2(__float2half_rn(v.z), __float2half_rn(v.w));
}

__global__ void transpose_qkv_kernel(const float* __restrict__ Wq,
                                     const float* __restrict__ Wk,
                                     const float* __restrict__ Wv,
                                     __half* __restrict__ T)
{
    __shared__ float t[32][33];
    const int z = blockIdx.z;
    const int Ndim = (z == 0) ? QD : KD;
    const int n0 = blockIdx.x * 32;
    if (n0 >= Ndim) return;
    const int k0 = blockIdx.y * 32;
    const float* W = (z == 0) ? Wq : (z == 1 ? Wk : Wv);
    __half* To = T + (size_t)((z == 0) ? 0 : (z == 1 ? QD : QD + KD)) * HID;
    const int tx = threadIdx.x, ty = threadIdx.y;
#pragma unroll
    for (int j = 0; j < 4; j++)
        t[ty + j * 8][tx] = W[(size_t)(k0 + ty + j * 8) * Ndim + n0 + tx];
    __syncthreads();
#pragma unroll
    for (int j = 0; j < 4; j++)
        To[(size_t)(n0 + ty + j * 8) * HID + k0 + tx] = __float2half_rn(t[tx][ty + j * 8]);
}

__global__ void transpose_h_kernel(const float* __restrict__ W,
                                   __half* __restrict__ T, int Kdim, int Ndim)
{
    __shared__ float t[32][33];
    const int k0 = blockIdx.y * 32, n0 = blockIdx.x * 32;
    const int tx = threadIdx.x, ty = threadIdx.y;
#pragma unroll
    for (int j = 0; j < 4; j++)
        t[ty + j * 8][tx] = W[(size_t)(k0 + ty + j * 8) * Ndim + n0 + tx];
    __syncthreads();
#pragma unroll
    for (int j = 0; j < 4; j++)
        T[(size_t)(n0 + ty + j * 8) * Kdim + k0 + tx] = __float2half_rn(t[tx][ty + j * 8]);
}

// ---------------------------------------------------------------------------
// single-fp16 GEMM, templated output type (fp32 for out-proj, fp16 for QKV)
// ---------------------------------------------------------------------------
#define SAB 72
#define TILE_E (128*SAB)
#define STG_E (2*TILE_E)
#define HGSM (2*STG_E*2)

template <typename OT>
__global__ __launch_bounds__(256, 2)
void hgemm(const __half* __restrict__ Ap, const __half* __restrict__ Bp,
           OT* __restrict__ C, int Ntot, int K)
{
    extern __shared__ __half sh16[];
    const int tid  = threadIdx.x;
    const int lane = tid & 31, wid = tid >> 5;
    const int wm = wid >> 2, wn = wid & 3;
    const int g = lane >> 2, t = lane & 3;
    const int m0 = blockIdx.y * 128, n0 = blockIdx.x * 128;

    const uint32_t sbase = (uint32_t)__cvta_generic_to_shared(sh16);
    const __half* baseA = Ap + (size_t)m0 * K;
    const __half* baseB = Bp + (size_t)n0 * K;

    float acc[4][4][4];
#pragma unroll
    for (int mt = 0; mt < 4; mt++)
#pragma unroll
        for (int nt = 0; nt < 4; nt++)
#pragma unroll
            for (int r = 0; r < 4; r++) acc[mt][nt][r] = 0.f;

    const int a_off = ((lane & 7) + ((lane >> 3) & 1) * 8) * SAB + ((lane >> 4) & 1) * 8;
    const int b_off = ((lane & 7) + ((lane >> 4) & 1) * 8) * SAB + ((lane >> 3) & 1) * 8;

    auto issue_copy = [&](int c, int buf) {
        const int koff = c * 64;
#pragma unroll
        for (int i = 0; i < 8; i++) {
            const int f = tid + i * 256;
            const int tl = f >> 10;
            const int slot = f & 1023;
            const int row = slot >> 3, seg = slot & 7;
            const __half* gp = (tl ? baseB : baseA) + (size_t)row * K + koff + seg * 8;
            const uint32_t dst = sbase +
                (uint32_t)(buf * STG_E + tl * TILE_E + row * SAB + seg * 8) * 2;
            cpasync16(dst, gp);
        }
        asm volatile("cp.async.commit_group;" ::: "memory");
    };

    const int nkb = K >> 6;
    issue_copy(0, 0);

    for (int kb = 0; kb < nkb; kb++) {
        const int cur = kb & 1;
        if (kb + 1 < nkb) {
            issue_copy(kb + 1, cur ^ 1);
            asm volatile("cp.async.wait_group 1;" ::: "memory");
        } else {
            asm volatile("cp.async.wait_group 0;" ::: "memory");
        }
        __syncthreads();

        const uint32_t sA = sbase + (uint32_t)(cur * STG_E) * 2;
        const uint32_t sB = sA + (uint32_t)TILE_E * 2;

#pragma unroll
        for (int ks = 0; ks < 4; ks++) {
            const int kbase = ks * 16;
            uint32_t af[4][4], bf[2][4];
#pragma unroll
            for (int mt = 0; mt < 4; mt++)
                ldsm4(af[mt], sA + (uint32_t)((wm * 64 + mt * 16) * SAB + kbase + a_off) * 2);
#pragma unroll
            for (int np = 0; np < 2; np++)
                ldsm4(bf[np], sB + (uint32_t)((wn * 32 + np * 16) * SAB + kbase + b_off) * 2);
#pragma unroll
            for (int mt = 0; mt < 4; mt++)
#pragma unroll
                for (int nt = 0; nt < 4; nt++) {
                    const int pr = nt >> 1, hf = (nt & 1) * 2;
                    uint32_t bb[2] = { bf[pr][hf], bf[pr][hf + 1] };
                    mma16h(acc[mt][nt], af[mt], bb);
                }
        }
        __syncthreads();
    }

#pragma unroll
    for (int mt = 0; mt < 4; mt++) {
        const int r0 = m0 + wm * 64 + mt * 16 + g;
#pragma unroll
        for (int nt = 0; nt < 4; nt++) {
            const int c0 = n0 + wn * 32 + nt * 8 + t * 2;
            if (sizeof(OT) == 4) {
                *(float2*)&((float*)C)[(size_t)r0 * Ntot + c0] =
                    make_float2(acc[mt][nt][0], acc[mt][nt][1]);
                *(float2*)&((float*)C)[(size_t)(r0 + 8) * Ntot + c0] =
                    make_float2(acc[mt][nt][2], acc[mt][nt][3]);
            } else {
                *(__half2*)&((__half*)C)[(size_t)r0 * Ntot + c0] =
                    __floats2half2_rn(acc[mt][nt][0], acc[mt][nt][1]);
                *(__half2*)&((__half*)C)[(size_t)(r0 + 8) * Ntot + c0] =
                    __floats2half2_rn(acc[mt][nt][2], acc[mt][nt][3]);
            }
        }
    }
}

// ---------------------------------------------------------------------------
// Unified norm/rope -> fp16 single: grid (L, 12), reads fp16 QKV.
// ---------------------------------------------------------------------------
__global__ __launch_bounds__(256)
void prep_qkv_kernel(const __half* __restrict__ QKV,
                     const float* __restrict__ qw,
                     const float* __restrict__ kw,
                     const float* __restrict__ cosp,
                     const float* __restrict__ sinp,
                     __half* __restrict__ Qo, __half* __restrict__ Ko)
{
    const int t = blockIdx.x;
    const int h = blockIdx.y;
    const int d = threadIdx.x;

    const bool isQ = (h < 8);
    const int hh = isQ ? h : h - 8;
    const float* w = isQ ? qw : kw;
    float x = __half2float(QKV[(size_t)t * QKVD + (isQ ? 0 : QD) + hh * HD + d]);

    float v = x * x;
#pragma unroll
    for (int o = 16; o; o >>= 1) v += __shfl_xor_sync(0xffffffffu, v, o);

    __shared__ float ws[8];
    __shared__ float buf[HD];
    if ((d & 31) == 0) ws[d >> 5] = v;
    __syncthreads();
    float ss = ws[0] + ws[1] + ws[2] + ws[3] + ws[4] + ws[5] + ws[6] + ws[7];

    float r = rsqrtf(ss * (1.0f / HD) + 1e-6f);
    float xn = x * r * (1.0f + w[d]);
    buf[d] = xn;
    __syncthreads();

    float rot = (d < HD / 2) ? -buf[d + HD / 2] : buf[d - HD / 2];
    float c = cosp[(size_t)t * HD + d];
    float s = sinp[(size_t)t * HD + d];
    float xr = xn * c + rot * s;

    const size_t oo = (size_t)t * (isQ ? QD : KD) + hh * HD + d;
    if (isQ) Qo[oo] = __float2half_rn(xr);
    else     Ko[oo] = __float2half_rn(xr);
}

// ---------------------------------------------------------------------------
// Flash attention, single fp16, BM=64 x BN=128 (round-14 winner; V read
// directly from fused QKV buffer via stride parameter).
// ---------------------------------------------------------------------------
#define SQF 264
#define SCF 72
#define SPF 136
#define CHUNK_E (128*SCF)              // 9216 halves per K/V chunk
#define P_E (64*SPF)                   // 8704
#define OQ2  0                         // Q: 64*SQF = 16896
#define OC2  (64*SQF)                  // 2 chunk slots
#define OP2  (OC2 + 2*CHUNK_E)         // P
#define OEND2 (OP2 + P_E)              // 44032 halves
#define ATTH_SMEM (OEND2*2 + 256*4)    // 89088 bytes

__global__ __launch_bounds__(256, 1)
void attn_h_kernel()
{
    extern __shared__ __half smh[];
    float* pm = (float*)(smh + OEND2);
    float* ps = pm + 128;

    const int qt  = (int)gridDim.x - 1 - (int)blockIdx.x;  // long rows first
    const int seq = blockIdx.y;
    const int h   = blockIdx.z;
    const int kvh = h >> 1;

    const int tid  = threadIdx.x;
    const int lane = tid & 31, wid = tid >> 5;
    const int wm = wid >> 1, wn = wid & 1;
    const int g = lane >> 2, t = lane & 3;

    const int t0 = seq * SEQ + qt * 64;
    const int ktmax = qt >> 1;
    const int doff = (qt & 1) * 64;
    const uint32_t sb = (uint32_t)__cvta_generic_to_shared(smh);

    const __half* Vbase = g_QKV16 + QD + KD;   // V inside fused buffer

    const int aoffQ = ((lane & 7) + ((lane >> 3) & 1) * 8) * SQF + ((lane >> 4) & 1) * 8;
    const int aoffP = ((lane & 7) + ((lane >> 3) & 1) * 8) * SPF + ((lane >> 4) & 1) * 8;
    const int boffK = ((lane & 7) + ((lane >> 4) & 1) * 8) * SCF + ((lane >> 3) & 1) * 8;
    const int voffV = ((lane & 7) + ((lane >> 3) & 1) * 8) * SCF + ((lane >> 4) & 1) * 8;

    // load one 128x64 fp16 chunk of K or V into slot buf (row stride param)
    auto issue_kv = [&](const __half* gsrc, int gstride, int k0, int dc, int buf) {
#pragma unroll
        for (int i = 0; i < 4; i++) {
            int f = tid + i * 256;          // 0..1023
            int row = f >> 3, seg = f & 7;
            const __half* gp = gsrc +
                (size_t)(k0 + row) * gstride + kvh * HD + dc * 64 + seg * 8;
            cpasync16(sb + (uint32_t)(OC2 + buf * CHUNK_E + row * SCF + seg * 8) * 2, gp);
        }
        asm volatile("cp.async.commit_group;" ::: "memory");
    };

    // prefetch K chunk0 of kt=0, then resident Q
    issue_kv(g_K16a, KD, seq * SEQ, 0, 0);
    {
        const __half* gq = g_Q16a + (size_t)t0 * QD + h * HD;
#pragma unroll
        for (int i = 0; i < 8; i++) {
            int f = tid + i * 256;
            int row = f >> 5, seg = f & 31;
            cpasync16(sb + (uint32_t)(OQ2 + row * SQF + seg * 8) * 2,
                      gq + (size_t)row * QD + seg * 8);
        }
        asm volatile("cp.async.commit_group;" ::: "memory");
        asm volatile("cp.async.wait_group 0;" ::: "memory");
    }
    __syncthreads();

    float O[4][4][4];
#pragma unroll
    for (int dc = 0; dc < 4; dc++)
#pragma unroll
        for (int nt = 0; nt < 4; nt++)
#pragma unroll
            for (int r = 0; r < 4; r++) O[dc][nt][r] = 0.f;
    float m0 = -INFINITY, m1 = -INFINITY, l0 = 0.f, l1 = 0.f;

    for (int kt = 0; kt <= ktmax; kt++) {
        const int k0 = seq * SEQ + kt * 128;

        float S[8][4];
#pragma unroll
        for (int nt = 0; nt < 8; nt++)
#pragma unroll
            for (int r = 0; r < 4; r++) S[nt][r] = 0.f;

        // ---- S = Q @ K^T over 4 d-chunks (K: 128 rows per chunk) ----
        for (int dc = 0; dc < 4; dc++) {
            const int buf = dc & 1;
            if (dc < 3) {
                issue_kv(g_K16a, KD, k0, dc + 1, buf ^ 1);
                asm volatile("cp.async.wait_group 1;" ::: "memory");
            } else {
                asm volatile("cp.async.wait_group 0;" ::: "memory");
            }
            __syncthreads();

            const int ok = OC2 + buf * CHUNK_E;
#pragma unroll
            for (int ks = 0; ks < 4; ks++) {
                const int kq = dc * 64 + ks * 16;
                uint32_t qf[4], kf[4][4];
                ldsm4(qf, sb + (uint32_t)(OQ2 + (wm * 16) * SQF + kq + aoffQ) * 2);
#pragma unroll
                for (int pr = 0; pr < 4; pr++) {
                    const int nb = (wn * 64 + pr * 16) * SCF + ks * 16;
                    ldsm4(kf[pr], sb + (uint32_t)(ok + nb + boffK) * 2);
                }
#pragma unroll
                for (int nt = 0; nt < 8; nt++) {
                    const int pr = nt >> 1, hf = (nt & 1) * 2;
                    uint32_t bb[2] = { kf[pr][hf], kf[pr][hf + 1] };
                    mma16h(S[nt], qf, bb);
                }
            }
            __syncthreads();
        }

        // V chunk0 prefetch overlaps softmax
        issue_kv(Vbase, QKVD, k0, 0, 0);

        // ---- scale + causal mask (last k-tile only) ----
#pragma unroll
        for (int nt = 0; nt < 8; nt++) {
#pragma unroll
            for (int r = 0; r < 4; r++) S[nt][r] *= SCALING;
            if (kt == ktmax) {
                const int cl = wn * 64 + nt * 8 + 2 * t;
                const int rl0 = wm * 16 + g + doff, rl1 = rl0 + 8;
                if (cl     > rl0) S[nt][0] = -INFINITY;
                if (cl + 1 > rl0) S[nt][1] = -INFINITY;
                if (cl     > rl1) S[nt][2] = -INFINITY;
                if (cl + 1 > rl1) S[nt][3] = -INFINITY;
            }
        }

        // ---- online softmax ----
        float rm0 = -INFINITY, rm1 = -INFINITY;
#pragma unroll
        for (int nt = 0; nt < 8; nt++) {
            rm0 = fmaxf(rm0, fmaxf(S[nt][0], S[nt][1]));
            rm1 = fmaxf(rm1, fmaxf(S[nt][2], S[nt][3]));
        }
        rm0 = fmaxf(rm0, __shfl_xor_sync(0xffffffffu, rm0, 1));
        rm0 = fmaxf(rm0, __shfl_xor_sync(0xffffffffu, rm0, 2));
        rm1 = fmaxf(rm1, __shfl_xor_sync(0xffffffffu, rm1, 1));
        rm1 = fmaxf(rm1, __shfl_xor_sync(0xffffffffu, rm1, 2));
        if (t == 0) {
            pm[wn * 64 + wm * 16 + g]     = rm0;
            pm[wn * 64 + wm * 16 + 8 + g] = rm1;
        }
        __syncthreads();
        rm0 = fmaxf(rm0, pm[(wn ^ 1) * 64 + wm * 16 + g]);
        rm1 = fmaxf(rm1, pm[(wn ^ 1) * 64 + wm * 16 + 8 + g]);

        const float mn0 = fmaxf(m0, rm0), mn1 = fmaxf(m1, rm1);
        const float a0 = __expf(m0 - mn0), a1 = __expf(m1 - mn1);

        float s0 = 0.f, s1 = 0.f;
#pragma unroll
        for (int nt = 0; nt < 8; nt++) {
            float p0 = __expf(S[nt][0] - mn0);
            float p1 = __expf(S[nt][1] - mn0);
            float p2 = __expf(S[nt][2] - mn1);
            float p3 = __expf(S[nt][3] - mn1);
            s0 += p0 + p1;
            s1 += p2 + p3;
            const int col = wn * 64 + nt * 8 + 2 * t;
            const int r0 = wm * 16 + g, r1 = r0 + 8;
            *(__half2*)&smh[OP2 + r0 * SPF + col] = __floats2half2_rn(p0, p1);
            *(__half2*)&smh[OP2 + r1 * SPF + col] = __floats2half2_rn(p2, p3);
        }
        s0 += __shfl_xor_sync(0xffffffffu, s0, 1);
        s0 += __shfl_xor_sync(0xffffffffu, s0, 2);
        s1 += __shfl_xor_sync(0xffffffffu, s1, 1);
        s1 += __shfl_xor_sync(0xffffffffu, s1, 2);
        if (t == 0) {
            ps[wn * 64 + wm * 16 + g]     = s0;
            ps[wn * 64 + wm * 16 + 8 + g] = s1;
        }
        __syncthreads();
        l0 = l0 * a0 + ps[wm * 16 + g]     + ps[64 + wm * 16 + g];
        l1 = l1 * a1 + ps[wm * 16 + 8 + g] + ps[64 + wm * 16 + 8 + g];
        m0 = mn0; m1 = mn1;
#pragma unroll
        for (int dc = 0; dc < 4; dc++)
#pragma unroll
            for (int nt = 0; nt < 4; nt++) {
                O[dc][nt][0] *= a0; O[dc][nt][1] *= a0;
                O[dc][nt][2] *= a1; O[dc][nt][3] *= a1;
            }

        // ---- O += P @ V; prefetch next-kt K during last chunk ----
        for (int dc = 0; dc < 4; dc++) {
            const int buf = dc & 1;
            if (dc < 3) {
                issue_kv(Vbase, QKVD, k0, dc + 1, buf ^ 1);
                asm volatile("cp.async.wait_group 1;" ::: "memory");
            } else {
                asm volatile("cp.async.wait_group 0;" ::: "memory");
                if (kt < ktmax) issue_kv(g_K16a, KD, k0 + 128, 0, 0);
            }
            __syncthreads();

            const int ok = OC2 + buf * CHUNK_E;
#pragma unroll
            for (int kk = 0; kk < 8; kk++) {
                uint32_t pf[4], vf[2][4];
                ldsm4(pf, sb + (uint32_t)(OP2 + (wm * 16) * SPF + kk * 16 + aoffP) * 2);
#pragma unroll
                for (int pr = 0; pr < 2; pr++) {
                    const int vb = (kk * 16) * SCF + wn * 32 + pr * 16;
                    ldsm4t(vf[pr], sb + (uint32_t)(ok + vb + voffV) * 2);
                }
#pragma unroll
                for (int nt = 0; nt < 4; nt++) {
                    const int pr = nt >> 1, hf = (nt & 1) * 2;
                    uint32_t bb[2] = { vf[pr][hf], vf[pr][hf + 1] };
                    mma16h(O[dc][nt], pf, bb);
                }
            }
            __syncthreads();
        }
    }

    // ---- epilogue: fp16 direct ----
    const float i0 = 1.0f / l0, i1 = 1.0f / l1;
#pragma unroll
    for (int dc = 0; dc < 4; dc++)
#pragma unroll
        for (int nt = 0; nt < 4; nt++) {
            const int col = h * HD + dc * 64 + wn * 32 + nt * 8 + 2 * t;
            const size_t r0 = (size_t)(t0 + wm * 16 + g) * QD + col;
            const size_t r1 = (size_t)(t0 + wm * 16 + 8 + g) * QD + col;
            *(__half2*)&g_A16[r0] =
                __floats2half2_rn(O[dc][nt][0] * i0, O[dc][nt][1] * i0);
            *(__half2*)&g_A16[r1] =
                __floats2half2_rn(O[dc][nt][2] * i1, O[dc][nt][3] * i1);
        }
}

// ---------------------------------------------------------------------------
// launch
// ---------------------------------------------------------------------------
extern "C" void kernel_launch(void* const* d_in, const int* in_sizes, int n_in,
                              void* d_out, int out_size)
{
    (void)in_sizes; (void)n_in; (void)out_size;
    const float* hs   = (const float*)d_in[0];
    const float* cosp = (const float*)d_in[1];
    const float* sinp = (const float*)d_in[2];
    const float* Wq   = (const float*)d_in[3];
    const float* Wk   = (const float*)d_in[4];
    const float* Wv   = (const float*)d_in[5];
    const float* Wo   = (const float*)d_in[6];
    const float* qw   = (const float*)d_in[7];
    const float* kw   = (const float*)d_in[8];
    float* out = (float*)d_out;

    __half *pQKV16, *phs, *pWqkv, *pWo, *pA16, *pQ16, *pK16;
    cudaGetSymbolAddress((void**)&pQKV16, g_QKV16);
    cudaGetSymbolAddress((void**)&phs,  g_hs16);
    cudaGetSymbolAddress((void**)&pWqkv, g_Wqkv16);
    cudaGetSymbolAddress((void**)&pWo,  g_Wo16);
    cudaGetSymbolAddress((void**)&pA16, g_A16);
    cudaGetSymbolAddress((void**)&pQ16, g_Q16a);
    cudaGetSymbolAddress((void**)&pK16, g_K16a);

    // 0. operand prep
    {
        int n = L * HID / 4;
        conv_h_kernel<<<(n + 255) / 256, 256>>>(hs, phs, n);
    }
    transpose_qkv_kernel<<<dim3(QD / 32, HID / 32, 3), dim3(32, 8)>>>(Wq, Wk, Wv, pWqkv);
    transpose_h_kernel<<<dim3(HID / 32, QD / 32), dim3(32, 8)>>>(Wo, pWo, QD, HID);

    cudaFuncSetAttribute(hgemm<__half>, cudaFuncAttributeMaxDynamicSharedMemorySize, HGSM);
    cudaFuncSetAttribute(hgemm<float>,  cudaFuncAttributeMaxDynamicSharedMemorySize, HGSM);

    // 1. fused QKV projection -> fp16 directly
    hgemm<__half><<<dim3(QKVD / 128, L / 128), 256, HGSM>>>(phs, pWqkv, pQKV16, QKVD, HID);

    // 2. unified RMSNorm/RoPE -> fp16 (V stays in fused buffer, no copy)
    prep_qkv_kernel<<<dim3(L, 12), 256>>>(pQKV16, qw, kw, cosp, sinp, pQ16, pK16);

    // 3. attention (round-14 winner, V via strided read)
    cudaFuncSetAttribute(attn_h_kernel,
                         cudaFuncAttributeMaxDynamicSharedMemorySize, ATTH_SMEM);
    attn_h_kernel<<<dim3(SEQ / 64, L / SEQ, NH), 256, ATTH_SMEM>>>();

    // 4. output projection -> fp32 harness buffer
    hgemm<float><<<dim3(HID / 128, L / 128), 256, HGSM>>>(pA16, pWo, out, HID, QD);
}